// round 1
// baseline (speedup 1.0000x reference)
#include <cuda_runtime.h>
#include <cstdint>
#include <cstddef>

#define NN   20000
#define NKG  50000
#define EE   320000
#define RR   8
#define HH   4
#define HD   256

// ---------------- device scratch (no allocations allowed) ----------------
__device__ float g_xin [(size_t)NN*HD];
__device__ float g_xw  [(size_t)RR*NN*HD];   // 160 MB
__device__ float g_s   [(size_t)NN*64];      // [n][j], j<32: q-part (r*4+h), j>=32: k-part
__device__ float g_wqk [256*64];
__device__ float g_exl [(size_t)EE*HH];      // logits, then exp()
__device__ float g_m   [NN*HH];
__device__ float g_ssum[NN*HH];
__device__ float g_agg [(size_t)NN*HD];
__device__ float g_x1  [(size_t)NN*HD];
__device__ float g_hs  [(size_t)NN*HD];
__device__ float g_skp [(size_t)NN*HD];

__device__ __forceinline__ float lrelu01(float v){ return v > 0.f ? v : 0.01f*v; }

__device__ __forceinline__ void atomicMaxF(float* a, float v){
    if (v >= 0.f) atomicMax((int*)a, __float_as_int(v));
    else          atomicMin((unsigned int*)a, __float_as_uint(v));
}

// ---------------- x_in = [kg_emb[nid] | ccle_mlp(ccle[nid])] ----------------
__global__ void build_xin(const float* __restrict__ kg, const float* __restrict__ ccle,
                          const int* __restrict__ nid,
                          const float* __restrict__ cw1, const float* __restrict__ cb1,
                          const float* __restrict__ cw2, const float* __restrict__ cb2)
{
    int i = blockIdx.x;
    int t = threadIdx.x;               // 128 threads
    int nd = nid[i];
    __shared__ float c4[4];
    __shared__ float hdn[32];
    if (t < 4) c4[t] = ccle[(size_t)nd*4 + t];
    g_xin[(size_t)i*HD + t] = kg[(size_t)nd*128 + t];
    __syncthreads();
    if (t < 32){
        float a = cb1[t];
        #pragma unroll
        for (int j = 0; j < 4; j++) a += c4[j]*cw1[j*32 + t];
        hdn[t] = lrelu01(a);
    }
    __syncthreads();
    float o = cb2[t];
    #pragma unroll 8
    for (int j = 0; j < 32; j++) o += hdn[j]*cw2[j*128 + t];
    g_xin[(size_t)i*HD + 128 + t] = o;
}

// ---------------- wqk[k][j] : fold w[r] @ q and w[r] @ k into 256x64 ----------------
__global__ void make_wqk(const float* __restrict__ w, const float* __restrict__ q,
                         const float* __restrict__ km)
{
    int idx = blockIdx.x*blockDim.x + threadIdx.x;   // 16384
    int kk  = idx >> 6;
    int j   = idx & 63;
    int isK = (j >= 32);
    int rh  = isK ? j - 32 : j;
    int r   = rh >> 2, h = rh & 3;
    const float* wm = w + ((size_t)r*256 + kk)*256;
    const float* qm = isK ? km : q;
    float a = 0.f;
    #pragma unroll 8
    for (int o = 0; o < 256; o++) a += wm[o]*qm[o*4 + h];
    g_wqk[kk*64 + j] = a;
}

// ---------------- generic K=256 GEMM: C[b] = A @ W[b] (+bias, act) ----------------
template<int BN>
__global__ void gemm_k256(const float* __restrict__ A,
                          const float* __restrict__ W,
                          float* __restrict__ C,
                          int M, int ldw, int ldc,
                          const float* __restrict__ bias, int act,
                          size_t wStride, size_t cStride)
{
    constexpr int BM = 64, BK = 16;
    constexpr int TN = BN/16;    // 8 (BN=128) or 4 (BN=64)
    constexpr int TM = 4;
    __shared__ float As[BK][BM + 4];
    __shared__ float Ws[BK][BN];

    const float* Wb = W + wStride*blockIdx.z;
    float*       Cb = C + cStride*blockIdx.z;
    int row0 = blockIdx.x*BM;
    int col0 = blockIdx.y*BN;
    int t  = threadIdx.x;
    int tx = t & 15, ty = t >> 4;

    float acc[TM][TN];
    #pragma unroll
    for (int i = 0; i < TM; i++)
        #pragma unroll
        for (int j = 0; j < TN; j++) acc[i][j] = 0.f;

    int aRow = t >> 2;
    int aK4  = (t & 3) * 4;

    for (int k0 = 0; k0 < 256; k0 += BK){
        float4 av = make_float4(0.f,0.f,0.f,0.f);
        int gr = row0 + aRow;
        if (gr < M) av = *(const float4*)(A + (size_t)gr*256 + k0 + aK4);
        As[aK4+0][aRow] = av.x; As[aK4+1][aRow] = av.y;
        As[aK4+2][aRow] = av.z; As[aK4+3][aRow] = av.w;
        #pragma unroll
        for (int l = 0; l < BN/64; l++){
            int idx = t + l*256;
            int kk  = idx / (BN/4);
            int j4  = (idx % (BN/4)) * 4;
            float4 wv = *(const float4*)(Wb + (size_t)(k0+kk)*ldw + col0 + j4);
            *(float4*)&Ws[kk][j4] = wv;
        }
        __syncthreads();
        #pragma unroll
        for (int kk = 0; kk < BK; kk++){
            float a[TM], bb[TN];
            #pragma unroll
            for (int i = 0; i < TM; i++) a[i] = As[kk][ty*TM + i];
            #pragma unroll
            for (int j = 0; j < TN; j++) bb[j] = Ws[kk][tx*TN + j];
            #pragma unroll
            for (int i = 0; i < TM; i++)
                #pragma unroll
                for (int j = 0; j < TN; j++) acc[i][j] += a[i]*bb[j];
        }
        __syncthreads();
    }

    #pragma unroll
    for (int i = 0; i < TM; i++){
        int gr = row0 + ty*TM + i;
        if (gr >= M) continue;
        #pragma unroll
        for (int j = 0; j < TN; j++){
            int gc = col0 + tx*TN + j;
            float v = acc[i][j];
            if (bias) v += bias[gc];
            if (act == 1) v = lrelu01(v);
            Cb[(size_t)gr*ldc + gc] = v;
        }
    }
}

// ---------------- init per-layer edge state ----------------
__global__ void init_state()
{
    int i = blockIdx.x*blockDim.x + threadIdx.x;
    if (i < NN*HD) g_agg[i] = 0.f;
    if (i < NN*HH){ g_m[i] = __int_as_float(0xff800000); g_ssum[i] = 0.f; }
}

// ---------------- edge logits + segment max ----------------
__global__ void edge_logit(const int* __restrict__ src, const int* __restrict__ dst,
                           const int* __restrict__ et)
{
    int e = blockIdx.x*blockDim.x + threadIdx.x;
    if (e >= EE) return;
    int s = src[e], d = dst[e], r = et[e];
    const float* qv = g_s + (size_t)d*64 + r*4;
    const float* kv = g_s + (size_t)s*64 + 32 + r*4;
    #pragma unroll
    for (int h = 0; h < HH; h++){
        float l = qv[h] + kv[h];
        l = l > 0.f ? l : 0.2f*l;           // leaky 0.2
        g_exl[(size_t)e*HH + h] = l;
        atomicMaxF(&g_m[d*HH + h], l);
    }
}

// ---------------- exp + segment sum ----------------
__global__ void edge_exp(const int* __restrict__ dst)
{
    int idx = blockIdx.x*blockDim.x + threadIdx.x;
    if (idx >= EE*HH) return;
    int e = idx >> 2, h = idx & 3;
    int d = dst[e];
    float v = expf(g_exl[idx] - g_m[d*HH + h]);
    g_exl[idx] = v;
    atomicAdd(&g_ssum[d*HH + h], v);
}

// ---------------- weighted message scatter: agg[dst] += alpha * xw[et, src] ----------------
__global__ void edge_msg(const int* __restrict__ src, const int* __restrict__ dst,
                         const int* __restrict__ et)
{
    int e    = (blockIdx.x*blockDim.x + threadIdx.x) >> 5;
    int lane = threadIdx.x & 31;
    if (e >= EE) return;
    int s = src[e], d = dst[e], r = et[e];
    float wt[HH];
    #pragma unroll
    for (int h = 0; h < HH; h++)
        wt[h] = g_exl[(size_t)e*HH + h] / fmaxf(g_ssum[d*HH + h], 1e-16f);

    const float4* row = (const float4*)(g_xw + ((size_t)r*NN + s)*HD);
    float* out = g_agg + (size_t)d*HD;

    float4 v = row[lane];
    int c = lane*4; float ww = wt[c >> 6];
    atomicAdd(out + c + 0, v.x*ww); atomicAdd(out + c + 1, v.y*ww);
    atomicAdd(out + c + 2, v.z*ww); atomicAdd(out + c + 3, v.w*ww);

    v = row[lane + 32];
    c = 128 + lane*4; ww = wt[c >> 6];
    atomicAdd(out + c + 0, v.x*ww); atomicAdd(out + c + 1, v.y*ww);
    atomicAdd(out + c + 2, v.z*ww); atomicAdd(out + c + 3, v.w*ww);
}

// ---------------- epilogues ----------------
__global__ void finish_layer1(const float* __restrict__ bias)
{
    int i = blockIdx.x*blockDim.x + threadIdx.x;
    if (i >= NN*HD) return;
    g_x1[i] = lrelu01(g_agg[i] + bias[i & 255]);
}

__global__ void final_combine(const float* __restrict__ bias2, float* __restrict__ out)
{
    int i = blockIdx.x*blockDim.x + threadIdx.x;
    if (i >= NN*HD) return;
    out[i] = lrelu01(g_agg[i] + bias2[i & 255] + g_skp[i]);
}

// ---------------- host ----------------
static float* sym(const void* s){ void* p = nullptr; cudaGetSymbolAddress(&p, s); return (float*)p; }

extern "C" void kernel_launch(void* const* d_in, const int* in_sizes, int n_in,
                              void* d_out, int out_size)
{
    // input-order detection: setup_inputs dict order vs reference arg order
    int iKG, iCCLE, iNID, iEI, iET, iCW1, iCB1, iCW2, iCB2,
        iW1, iQ1, iK1, iB1, iW2, iQ2, iK2, iB2, iSW1, iSB1, iSW2, iSB2;
    if (in_sizes[2] == NN){   // setup_inputs order
        iKG=0; iCCLE=1; iNID=2; iEI=3; iET=4;
        iCW1=5; iCB1=6; iCW2=7; iCB2=8;
        iW1=9; iQ1=10; iK1=11; iB1=12;
        iW2=13; iQ2=14; iK2=15; iB2=16;
        iSW1=17; iSB1=18; iSW2=19; iSB2=20;
    } else {                  // reference signature order
        iKG=0; iCCLE=1;
        iCW1=2; iCB1=3; iCW2=4; iCB2=5;
        iW1=6; iQ1=7; iK1=8; iB1=9;
        iW2=10; iQ2=11; iK2=12; iB2=13;
        iSW1=14; iSB1=15; iSW2=16; iSB2=17;
        iNID=18; iEI=19; iET=20;
    }
    const float* kg   = (const float*)d_in[iKG];
    const float* ccle = (const float*)d_in[iCCLE];
    const int*   nid  = (const int*)  d_in[iNID];
    const int*   ei   = (const int*)  d_in[iEI];
    const int*   et   = (const int*)  d_in[iET];
    const int*   src  = ei;
    const int*   dst  = ei + EE;
    const float* cw1  = (const float*)d_in[iCW1];
    const float* cb1  = (const float*)d_in[iCB1];
    const float* cw2  = (const float*)d_in[iCW2];
    const float* cb2  = (const float*)d_in[iCB2];
    const float* w1   = (const float*)d_in[iW1];
    const float* q1   = (const float*)d_in[iQ1];
    const float* k1   = (const float*)d_in[iK1];
    const float* b1   = (const float*)d_in[iB1];
    const float* w2   = (const float*)d_in[iW2];
    const float* q2   = (const float*)d_in[iQ2];
    const float* k2   = (const float*)d_in[iK2];
    const float* b2   = (const float*)d_in[iB2];
    const float* sw1  = (const float*)d_in[iSW1];
    const float* sb1  = (const float*)d_in[iSB1];
    const float* sw2  = (const float*)d_in[iSW2];
    const float* sb2  = (const float*)d_in[iSB2];

    float* pxin = sym(g_xin);  float* pxw  = sym(g_xw);
    float* ps   = sym(g_s);    float* pwqk = sym(g_wqk);
    float* px1  = sym(g_x1);   float* phs  = sym(g_hs);
    float* pskp = sym(g_skp);

    const int gx = (NN + 63)/64;                  // 313
    const int eltBlocks = (NN*HD + 255)/256;      // 20000

    // x_in
    build_xin<<<NN, 128>>>(kg, ccle, nid, cw1, cb1, cw2, cb2);

    // ===== layer 1 =====
    make_wqk<<<64, 256>>>(w1, q1, k1);
    gemm_k256<64> <<<dim3(gx,1,1), 256>>>(pxin, pwqk, ps, NN, 64, 64, nullptr, 0, 0, 0);
    gemm_k256<128><<<dim3(gx,2,RR), 256>>>(pxin, w1, pxw, NN, 256, 256, nullptr, 0,
                                           (size_t)256*256, (size_t)NN*HD);
    init_state<<<eltBlocks, 256>>>();
    edge_logit<<<(EE+255)/256, 256>>>(src, dst, et);
    edge_exp  <<<(EE*HH+255)/256, 256>>>(dst);
    edge_msg  <<<(EE*32+255)/256, 256>>>(src, dst, et);
    finish_layer1<<<eltBlocks, 256>>>(b1);

    // ===== layer 2 =====
    make_wqk<<<64, 256>>>(w2, q2, k2);
    gemm_k256<64> <<<dim3(gx,1,1), 256>>>(px1, pwqk, ps, NN, 64, 64, nullptr, 0, 0, 0);
    gemm_k256<128><<<dim3(gx,2,RR), 256>>>(px1, w2, pxw, NN, 256, 256, nullptr, 0,
                                           (size_t)256*256, (size_t)NN*HD);
    init_state<<<eltBlocks, 256>>>();
    edge_logit<<<(EE+255)/256, 256>>>(src, dst, et);
    edge_exp  <<<(EE*HH+255)/256, 256>>>(dst);
    edge_msg  <<<(EE*32+255)/256, 256>>>(src, dst, et);

    // ===== skip path =====
    gemm_k256<128><<<dim3(gx,2,1), 256>>>(pxin, sw1, phs, NN, 256, 256, sb1, 1, 0, 0);
    gemm_k256<128><<<dim3(gx,2,1), 256>>>(phs, sw2, pskp, NN, 256, 256, sb2, 0, 0, 0);

    // ===== combine =====
    final_combine<<<eltBlocks, 256>>>(b2, (float*)d_out);
}

// round 2
// speedup vs baseline: 1.5087x; 1.5087x over previous
#include <cuda_runtime.h>
#include <cstdint>
#include <cstddef>

#define NN   20000
#define NKG  50000
#define EE   320000
#define RR   8
#define HH   4
#define HD   256

// ---------------- device scratch (no allocations allowed) ----------------
__device__ float g_xin [(size_t)NN*HD];
__device__ float g_xw  [(size_t)RR*NN*HD];   // 160 MB
__device__ float g_s   [(size_t)NN*64];      // [n][j], j<32: q-part (r*4+h), j>=32: k-part
__device__ float g_wqk [256*64];
__device__ float g_x1  [(size_t)NN*HD];
__device__ float g_hs  [(size_t)NN*HD];
__device__ float g_skp [(size_t)NN*HD];
// CSR by destination (rebuilt every launch; graph inputs are the same both layers)
__device__ int g_deg   [NN];
__device__ int g_rowptr[NN];
__device__ int g_cur   [NN];
__device__ int g_eid   [EE];

__device__ __forceinline__ float lrelu01(float v){ return v > 0.f ? v : 0.01f*v; }

// ---------------- x_in = [kg_emb[nid] | ccle_mlp(ccle[nid])] ----------------
__global__ void build_xin(const float* __restrict__ kg, const float* __restrict__ ccle,
                          const int* __restrict__ nid,
                          const float* __restrict__ cw1, const float* __restrict__ cb1,
                          const float* __restrict__ cw2, const float* __restrict__ cb2)
{
    int i = blockIdx.x;
    int t = threadIdx.x;               // 128 threads
    int nd = nid[i];
    __shared__ float c4[4];
    __shared__ float hdn[32];
    if (t < 4) c4[t] = ccle[(size_t)nd*4 + t];
    g_xin[(size_t)i*HD + t] = kg[(size_t)nd*128 + t];
    __syncthreads();
    if (t < 32){
        float a = cb1[t];
        #pragma unroll
        for (int j = 0; j < 4; j++) a += c4[j]*cw1[j*32 + t];
        hdn[t] = lrelu01(a);
    }
    __syncthreads();
    float o = cb2[t];
    #pragma unroll 8
    for (int j = 0; j < 32; j++) o += hdn[j]*cw2[j*128 + t];
    g_xin[(size_t)i*HD + 128 + t] = o;
}

// ---------------- wqk[k][j] : fold w[r] @ q and w[r] @ k into 256x64 ----------------
__global__ void make_wqk(const float* __restrict__ w, const float* __restrict__ q,
                         const float* __restrict__ km)
{
    int idx = blockIdx.x*blockDim.x + threadIdx.x;   // 16384
    int kk  = idx >> 6;
    int j   = idx & 63;
    int isK = (j >= 32);
    int rh  = isK ? j - 32 : j;
    int r   = rh >> 2, h = rh & 3;
    const float* wm = w + ((size_t)r*256 + kk)*256;
    const float* qm = isK ? km : q;
    float a = 0.f;
    #pragma unroll 8
    for (int o = 0; o < 256; o++) a += wm[o]*qm[o*4 + h];
    g_wqk[kk*64 + j] = a;
}

// ---------------- small GEMM (N=64) for attention projections ----------------
__global__ void gemm_k256_n64(const float* __restrict__ A, const float* __restrict__ W,
                              float* __restrict__ C, int M)
{
    constexpr int BM = 64, BK = 16, BN = 64;
    constexpr int TN = 4, TM = 4;
    __shared__ float As[BK][BM + 4];
    __shared__ float Ws[BK][BN];
    int row0 = blockIdx.x*BM;
    int t  = threadIdx.x;
    int tx = t & 15, ty = t >> 4;
    float acc[TM][TN] = {};
    int aRow = t >> 2;
    int aK4  = (t & 3) * 4;
    for (int k0 = 0; k0 < 256; k0 += BK){
        float4 av = make_float4(0.f,0.f,0.f,0.f);
        int gr = row0 + aRow;
        if (gr < M) av = *(const float4*)(A + (size_t)gr*256 + k0 + aK4);
        As[aK4+0][aRow] = av.x; As[aK4+1][aRow] = av.y;
        As[aK4+2][aRow] = av.z; As[aK4+3][aRow] = av.w;
        {
            int kk  = t / 16;
            int j4  = (t % 16) * 4;
            *(float4*)&Ws[kk][j4] = *(const float4*)(W + (size_t)(k0+kk)*64 + j4);
        }
        __syncthreads();
        #pragma unroll
        for (int kk = 0; kk < BK; kk++){
            float a[TM], bb[TN];
            #pragma unroll
            for (int i = 0; i < TM; i++) a[i] = As[kk][ty*TM + i];
            #pragma unroll
            for (int j = 0; j < TN; j++) bb[j] = Ws[kk][tx*TN + j];
            #pragma unroll
            for (int i = 0; i < TM; i++)
                #pragma unroll
                for (int j = 0; j < TN; j++) acc[i][j] += a[i]*bb[j];
        }
        __syncthreads();
    }
    #pragma unroll
    for (int i = 0; i < TM; i++){
        int gr = row0 + ty*TM + i;
        if (gr >= M) continue;
        #pragma unroll
        for (int j = 0; j < TN; j++)
            C[(size_t)gr*64 + tx*TN + j] = acc[i][j];
    }
}

// ---------------- big GEMM: 128x128 tile, 8x8 microtile, float4 ----------------
template<int ACT>
__global__ void __launch_bounds__(256, 2)
gemm128(const float* __restrict__ A, const float* __restrict__ W,
        float* __restrict__ C, int M, const float* __restrict__ bias,
        size_t wStride, size_t cStride)
{
    __shared__ float As[16][132];   // [k][m] transposed, rows 16B-aligned (132*4=528)
    __shared__ float Ws[16][128];   // [k][n]
    const float* Wb = W + wStride*blockIdx.z;
    float*       Cb = C + cStride*blockIdx.z;
    int row0 = blockIdx.x*128, col0 = blockIdx.y*128;
    int t  = threadIdx.x;
    int tx = t & 15, ty = t >> 4;

    float acc[8][8];
    #pragma unroll
    for (int i = 0; i < 8; i++)
        #pragma unroll
        for (int j = 0; j < 8; j++) acc[i][j] = 0.f;

    for (int k0 = 0; k0 < 256; k0 += 16){
        #pragma unroll
        for (int i = 0; i < 2; i++){
            int v   = t + i*256;
            int row = v >> 2;
            int kc  = (v & 3)*4;
            float4 av = make_float4(0.f,0.f,0.f,0.f);
            int gr = row0 + row;
            if (gr < M) av = *(const float4*)(A + (size_t)gr*256 + k0 + kc);
            As[kc+0][row] = av.x; As[kc+1][row] = av.y;
            As[kc+2][row] = av.z; As[kc+3][row] = av.w;
        }
        #pragma unroll
        for (int i = 0; i < 2; i++){
            int v  = t + i*256;
            int kr = v >> 5;
            int c4 = (v & 31)*4;
            *(float4*)&Ws[kr][c4] = *(const float4*)(Wb + (size_t)(k0+kr)*256 + col0 + c4);
        }
        __syncthreads();
        #pragma unroll
        for (int kk = 0; kk < 16; kk++){
            float a[8], b[8];
            *(float4*)&a[0] = *(const float4*)&As[kk][ty*8];
            *(float4*)&a[4] = *(const float4*)&As[kk][ty*8 + 4];
            *(float4*)&b[0] = *(const float4*)&Ws[kk][tx*8];
            *(float4*)&b[4] = *(const float4*)&Ws[kk][tx*8 + 4];
            #pragma unroll
            for (int i = 0; i < 8; i++)
                #pragma unroll
                for (int j = 0; j < 8; j++) acc[i][j] += a[i]*b[j];
        }
        __syncthreads();
    }

    #pragma unroll
    for (int i = 0; i < 8; i++){
        int gr = row0 + ty*8 + i;
        if (gr >= M) continue;
        #pragma unroll
        for (int j = 0; j < 8; j++){
            int gc = col0 + tx*8 + j;
            float v = acc[i][j];
            if (bias) v += bias[gc];
            if (ACT == 1) v = lrelu01(v);
            Cb[(size_t)gr*256 + gc] = v;
        }
    }
}

// ---------------- CSR build ----------------
__global__ void zero_deg(){
    int i = blockIdx.x*blockDim.x + threadIdx.x;
    if (i < NN) g_deg[i] = 0;
}
__global__ void hist(const int* __restrict__ dst){
    int e = blockIdx.x*blockDim.x + threadIdx.x;
    if (e < EE) atomicAdd(&g_deg[dst[e]], 1);
}
__global__ void scan_rowptr(){
    __shared__ int part[1024];
    int t = threadIdx.x;
    int beg = t*20, end = beg + 20; if (end > NN) end = NN;
    int s = 0;
    for (int i = beg; i < end && i < NN; i++) s += g_deg[i];
    part[t] = s;
    __syncthreads();
    for (int off = 1; off < 1024; off <<= 1){
        int v = 0;
        if (t >= off) v = part[t - off];
        __syncthreads();
        part[t] += v;
        __syncthreads();
    }
    int run = (t == 0) ? 0 : part[t-1];
    for (int i = beg; i < end && i < NN; i++){
        g_rowptr[i] = run;
        g_cur[i]    = run;
        run += g_deg[i];
    }
}
__global__ void scatter(const int* __restrict__ dst){
    int e = blockIdx.x*blockDim.x + threadIdx.x;
    if (e >= EE) return;
    int slot = atomicAdd(&g_cur[dst[e]], 1);
    g_eid[slot] = e;
}

// ---------------- fused per-destination attention + aggregation ----------------
// one block (128 thr) per dst node: logits -> online softmax -> weighted gather-sum
__global__ void edge_fused(const int* __restrict__ src, const int* __restrict__ et,
                           const float* __restrict__ bias,
                           const float* __restrict__ skip,   // nullable
                           float* __restrict__ out)
{
    const int d = blockIdx.x;
    const int t = threadIdx.x;          // 128
    const int wid  = t >> 5, lane = t & 31;
    const int base = g_rowptr[d], deg = g_deg[d];
    const int h0 = t >> 6;              // head for col t       (0..1)
    const int h1 = 2 + (t >> 6);        // head for col t+128   (2..3)

    __shared__ float sl[128][4];
    __shared__ int   ssrc[128];
    __shared__ int   srel[128];
    __shared__ float redm[4][4];
    __shared__ float reds[4][4];

    float acc0 = 0.f, acc1 = 0.f;
    float m[4], ssum[4];
    #pragma unroll
    for (int h = 0; h < 4; h++){ m[h] = -1e30f; ssum[h] = 0.f; }

    for (int c0 = 0; c0 < deg; c0 += 128){
        int n = deg - c0; if (n > 128) n = 128;
        float l[4];
        if (t < n){
            int e = g_eid[base + c0 + t];
            int s = src[e], r = et[e];
            ssrc[t] = s; srel[t] = r;
            const float* qv = g_s + (size_t)d*64 + r*4;
            const float* kv = g_s + (size_t)s*64 + 32 + r*4;
            #pragma unroll
            for (int h = 0; h < 4; h++){
                float v = qv[h] + kv[h];
                l[h] = v > 0.f ? v : 0.2f*v;
            }
        } else {
            #pragma unroll
            for (int h = 0; h < 4; h++) l[h] = -1e30f;
        }
        // block max per head
        float lm[4];
        #pragma unroll
        for (int h = 0; h < 4; h++){
            float v = l[h];
            #pragma unroll
            for (int o = 16; o; o >>= 1) v = fmaxf(v, __shfl_xor_sync(0xffffffffu, v, o));
            lm[h] = v;
        }
        if (lane == 0){
            #pragma unroll
            for (int h = 0; h < 4; h++) redm[wid][h] = lm[h];
        }
        __syncthreads();
        float newm[4], scale[4];
        #pragma unroll
        for (int h = 0; h < 4; h++){
            float cm = fmaxf(fmaxf(redm[0][h], redm[1][h]), fmaxf(redm[2][h], redm[3][h]));
            newm[h]  = fmaxf(m[h], cm);
            scale[h] = __expf(m[h] - newm[h]);
            m[h]     = newm[h];
            ssum[h] *= scale[h];
        }
        acc0 *= scale[h0];
        acc1 *= scale[h1];
        // exp weights + chunk sums
        float es[4];
        #pragma unroll
        for (int h = 0; h < 4; h++){
            float e = (t < n) ? __expf(l[h] - newm[h]) : 0.f;
            sl[t][h] = e;
            #pragma unroll
            for (int o = 16; o; o >>= 1) e += __shfl_xor_sync(0xffffffffu, e, o);
            es[h] = e;
        }
        if (lane == 0){
            #pragma unroll
            for (int h = 0; h < 4; h++) reds[wid][h] = es[h];
        }
        __syncthreads();
        #pragma unroll
        for (int h = 0; h < 4; h++)
            ssum[h] += reds[0][h] + reds[1][h] + reds[2][h] + reds[3][h];

        // weighted message accumulation (coalesced xw row reads, no atomics)
        for (int i = 0; i < n; i++){
            const float* row = g_xw + ((size_t)srel[i]*NN + ssrc[i])*HD;
            float w0 = sl[i][h0];
            float w1 = sl[i][h1];
            acc0 += w0 * row[t];
            acc1 += w1 * row[t + 128];
        }
        __syncthreads();
    }

    float inv0 = 1.f / fmaxf(ssum[h0], 1e-16f);
    float inv1 = 1.f / fmaxf(ssum[h1], 1e-16f);
    float v0 = acc0*inv0 + bias[t];
    float v1 = acc1*inv1 + bias[t + 128];
    if (skip){
        v0 += skip[(size_t)d*HD + t];
        v1 += skip[(size_t)d*HD + t + 128];
    }
    out[(size_t)d*HD + t]       = lrelu01(v0);
    out[(size_t)d*HD + t + 128] = lrelu01(v1);
}

// ---------------- host ----------------
static float* sym(const void* s){ void* p = nullptr; cudaGetSymbolAddress(&p, s); return (float*)p; }

extern "C" void kernel_launch(void* const* d_in, const int* in_sizes, int n_in,
                              void* d_out, int out_size)
{
    int iKG, iCCLE, iNID, iEI, iET, iCW1, iCB1, iCW2, iCB2,
        iW1, iQ1, iK1, iB1, iW2, iQ2, iK2, iB2, iSW1, iSB1, iSW2, iSB2;
    if (in_sizes[2] == NN){   // setup_inputs dict order
        iKG=0; iCCLE=1; iNID=2; iEI=3; iET=4;
        iCW1=5; iCB1=6; iCW2=7; iCB2=8;
        iW1=9; iQ1=10; iK1=11; iB1=12;
        iW2=13; iQ2=14; iK2=15; iB2=16;
        iSW1=17; iSB1=18; iSW2=19; iSB2=20;
    } else {                  // reference signature order
        iKG=0; iCCLE=1;
        iCW1=2; iCB1=3; iCW2=4; iCB2=5;
        iW1=6; iQ1=7; iK1=8; iB1=9;
        iW2=10; iQ2=11; iK2=12; iB2=13;
        iSW1=14; iSB1=15; iSW2=16; iSB2=17;
        iNID=18; iEI=19; iET=20;
    }
    const float* kg   = (const float*)d_in[iKG];
    const float* ccle = (const float*)d_in[iCCLE];
    const int*   nid  = (const int*)  d_in[iNID];
    const int*   ei   = (const int*)  d_in[iEI];
    const int*   et   = (const int*)  d_in[iET];
    const int*   src  = ei;
    const int*   dst  = ei + EE;
    const float* cw1  = (const float*)d_in[iCW1];
    const float* cb1  = (const float*)d_in[iCB1];
    const float* cw2  = (const float*)d_in[iCW2];
    const float* cb2  = (const float*)d_in[iCB2];
    const float* w1   = (const float*)d_in[iW1];
    const float* q1   = (const float*)d_in[iQ1];
    const float* k1   = (const float*)d_in[iK1];
    const float* b1   = (const float*)d_in[iB1];
    const float* w2   = (const float*)d_in[iW2];
    const float* q2   = (const float*)d_in[iQ2];
    const float* k2   = (const float*)d_in[iK2];
    const float* b2   = (const float*)d_in[iB2];
    const float* sw1  = (const float*)d_in[iSW1];
    const float* sb1  = (const float*)d_in[iSB1];
    const float* sw2  = (const float*)d_in[iSW2];
    const float* sb2  = (const float*)d_in[iSB2];

    float* pxin = sym(g_xin);  float* pxw  = sym(g_xw);
    float* ps   = sym(g_s);    float* pwqk = sym(g_wqk);
    float* px1  = sym(g_x1);   float* phs  = sym(g_hs);
    float* pskp = sym(g_skp);

    const int gM  = (NN + 127)/128;   // 157
    const int gM64= (NN + 63)/64;     // 313
    const int gE  = (EE + 255)/256;

    // x_in + CSR (once; reused by both layers)
    build_xin<<<NN, 128>>>(kg, ccle, nid, cw1, cb1, cw2, cb2);
    zero_deg<<<(NN+255)/256, 256>>>();
    hist<<<gE, 256>>>(dst);
    scan_rowptr<<<1, 1024>>>();
    scatter<<<gE, 256>>>(dst);

    // skip path (independent of layers)
    gemm128<1><<<dim3(gM,2,1), 256>>>(pxin, sw1, phs, NN, sb1, 0, 0);
    gemm128<0><<<dim3(gM,2,1), 256>>>(phs, sw2, pskp, NN, sb2, 0, 0);

    // ===== layer 1 =====
    make_wqk<<<64, 256>>>(w1, q1, k1);
    gemm_k256_n64<<<gM64, 256>>>(pxin, pwqk, ps, NN);
    gemm128<0><<<dim3(gM,2,RR), 256>>>(pxin, w1, pxw, NN, nullptr,
                                       (size_t)256*256, (size_t)NN*HD);
    edge_fused<<<NN, 128>>>(src, et, b1, nullptr, px1);

    // ===== layer 2 =====
    make_wqk<<<64, 256>>>(w2, q2, k2);
    gemm_k256_n64<<<gM64, 256>>>(px1, pwqk, ps, NN);
    gemm128<0><<<dim3(gM,2,RR), 256>>>(px1, w2, pxw, NN, nullptr,
                                       (size_t)256*256, (size_t)NN*HD);
    edge_fused<<<NN, 128>>>(src, et, b2, pskp, (float*)d_out);
}

// round 4
// speedup vs baseline: 3.0432x; 2.0172x over previous
#include <cuda_runtime.h>
#include <cuda_bf16.h>
#include <cstdint>
#include <cstddef>

#define NN   20000
#define EE   320000
#define RR   8
#define HH   4
#define HD   256

typedef __nv_bfloat16 bf16;

// ---------------- device scratch ----------------
__device__ float g_xin [(size_t)NN*HD];
__device__ float g_xw  [(size_t)RR*NN*HD];
__device__ float g_s   [(size_t)NN*64];
__device__ float g_wqk [256*64];
__device__ float g_x1  [(size_t)NN*HD];
__device__ float g_skp [(size_t)NN*HD];
__device__ bf16  g_xinh[(size_t)NN*HD];
__device__ bf16  g_xinl[(size_t)NN*HD];
__device__ bf16  g_x1h [(size_t)NN*HD];
__device__ bf16  g_x1l [(size_t)NN*HD];
__device__ bf16  g_hsh [(size_t)NN*HD];
__device__ bf16  g_hsl [(size_t)NN*HD];
__device__ bf16  g_w1h [(size_t)RR*65536];
__device__ bf16  g_w1l [(size_t)RR*65536];
__device__ bf16  g_w2h [(size_t)RR*65536];
__device__ bf16  g_w2l [(size_t)RR*65536];
__device__ bf16  g_sw1h[65536];
__device__ bf16  g_sw1l[65536];
__device__ bf16  g_sw2h[65536];
__device__ bf16  g_sw2l[65536];
__device__ int g_deg[NN], g_rowptr[NN], g_cur[NN], g_eid[EE];

__device__ __forceinline__ float lrelu01(float v){ return v > 0.f ? v : 0.01f*v; }

__device__ __forceinline__ uint32_t smem_u32(const void* p){
    uint32_t a;
    asm("{ .reg .u64 t; cvta.to.shared.u64 t, %1; cvt.u32.u64 %0, t; }" : "=r"(a) : "l"(p));
    return a;
}
__device__ __forceinline__ void ldsm_x4(uint32_t* r, uint32_t addr){
    asm volatile("ldmatrix.sync.aligned.m8n8.x4.shared.b16 {%0,%1,%2,%3}, [%4];"
        : "=r"(r[0]), "=r"(r[1]), "=r"(r[2]), "=r"(r[3]) : "r"(addr));
}
__device__ __forceinline__ void mma16816(float* d, const uint32_t* a, const uint32_t* b){
    asm volatile("mma.sync.aligned.m16n8k16.row.col.f32.bf16.bf16.f32 "
        "{%0,%1,%2,%3}, {%4,%5,%6,%7}, {%8,%9}, {%0,%1,%2,%3};"
        : "+f"(d[0]), "+f"(d[1]), "+f"(d[2]), "+f"(d[3])
        : "r"(a[0]), "r"(a[1]), "r"(a[2]), "r"(a[3]), "r"(b[0]), "r"(b[1]));
}

__device__ __forceinline__ void split2(float v, bf16& h, bf16& l){
    h = __float2bfloat16(v);
    l = __float2bfloat16(v - __bfloat162float(h));
}

// ---------------- x_in = [kg_emb[nid] | ccle_mlp(ccle[nid])] + bf16 splits ----------------
__global__ void build_xin(const float* __restrict__ kg, const float* __restrict__ ccle,
                          const int* __restrict__ nid,
                          const float* __restrict__ cw1, const float* __restrict__ cb1,
                          const float* __restrict__ cw2, const float* __restrict__ cb2)
{
    int i = blockIdx.x;
    int t = threadIdx.x;               // 128
    int nd = nid[i];
    __shared__ float c4[4];
    __shared__ float hdn[32];
    if (t < 4) c4[t] = ccle[(size_t)nd*4 + t];
    float v0 = kg[(size_t)nd*128 + t];
    g_xin[(size_t)i*HD + t] = v0;
    bf16 h, l; split2(v0, h, l);
    g_xinh[(size_t)i*HD + t] = h; g_xinl[(size_t)i*HD + t] = l;
    __syncthreads();
    if (t < 32){
        float a = cb1[t];
        #pragma unroll
        for (int j = 0; j < 4; j++) a += c4[j]*cw1[j*32 + t];
        hdn[t] = lrelu01(a);
    }
    __syncthreads();
    float o = cb2[t];
    #pragma unroll 8
    for (int j = 0; j < 32; j++) o += hdn[j]*cw2[j*128 + t];
    g_xin[(size_t)i*HD + 128 + t] = o;
    split2(o, h, l);
    g_xinh[(size_t)i*HD + 128 + t] = h; g_xinl[(size_t)i*HD + 128 + t] = l;
}

// ---------------- W split-transpose: w[z][k][n] -> wt[z][n][k] bf16 h/l ----------------
__global__ void splitW(const float* __restrict__ w, bf16* __restrict__ oh, bf16* __restrict__ ol)
{
    __shared__ float tile[32][33];
    int z = blockIdx.z;
    const float* wz = w + (size_t)z*65536;
    int tx = threadIdx.x, ty = threadIdx.y;   // 32x8
    int k0 = blockIdx.x*32, n0 = blockIdx.y*32;
    #pragma unroll
    for (int i = ty; i < 32; i += 8)
        tile[i][tx] = wz[(size_t)(k0+i)*256 + n0 + tx];
    __syncthreads();
    #pragma unroll
    for (int i = ty; i < 32; i += 8){
        float v = tile[tx][i];
        bf16 h, l; split2(v, h, l);
        size_t o = (size_t)z*65536 + (size_t)(n0+i)*256 + k0 + tx;
        oh[o] = h; ol[o] = l;
    }
}

// ---------------- HMMA GEMM: C[z][M,256-half] = A[M,256] @ Wt[z]^T ----------------
// Wt is [N,K] K-major. 2-term compensated bf16: Ah*Wh + Al*Wh + Ah*Wl, fp32 acc.
// MODE 0: fp32 -> Cf. MODE 1: bias+lrelu -> split to Ch/Cl. MODE 2: bias -> Cf.
template<int MODE>
__global__ void __launch_bounds__(256, 2)
hmma_gemm(const bf16* __restrict__ Ah, const bf16* __restrict__ Al,
          const bf16* __restrict__ Wh, const bf16* __restrict__ Wl,
          float* __restrict__ Cf, bf16* __restrict__ Ch, bf16* __restrict__ Cl,
          int M, const float* __restrict__ bias,
          size_t wStride, size_t cStride)
{
    extern __shared__ bf16 sm[];
    constexpr int P = 72;                       // pitch (bf16) -> 144B rows, LDSM conflict-free
    constexpr uint32_t SZ = 128*P*2;            // 18432 B per matrix
    const int t = threadIdx.x, lane = t & 31, wid = t >> 5;
    const int wm = wid & 3, wn = wid >> 2;      // 4x2 warp grid
    const int row0 = blockIdx.x*128;
    const int col0 = blockIdx.y*128;
    const bf16* WhB = Wh + wStride*blockIdx.z + (size_t)col0*256;
    const bf16* WlB = Wl + wStride*blockIdx.z + (size_t)col0*256;

    float acc[2][8][4];
    #pragma unroll
    for (int i = 0; i < 2; i++)
        #pragma unroll
        for (int j = 0; j < 8; j++)
            #pragma unroll
            for (int q = 0; q < 4; q++) acc[i][j][q] = 0.f;

    const uint32_t sb = smem_u32(sm);
    const int ar  = lane & 15, ac8 = lane >> 4;              // A ldmatrix addressing
    const int bnl = (lane & 7) + ((lane >> 4) << 3);         // B ldmatrix addressing
    const int bkh = (lane >> 3) & 1;

    for (int kc = 0; kc < 4; kc++){
        const int kofs = kc*64;
        #pragma unroll
        for (int i = 0; i < 4; i++){
            int linear = i*2048 + t*8;
            int row = linear >> 6, col = linear & 63;
            uint4 vh = make_uint4(0,0,0,0), vl = vh;
            int gr = row0 + row;
            if (gr < M){
                vh = *(const uint4*)(Ah + (size_t)gr*256 + kofs + col);
                vl = *(const uint4*)(Al + (size_t)gr*256 + kofs + col);
            }
            *(uint4*)(sm + row*P + col)           = vh;
            *(uint4*)(sm + 128*P + row*P + col)   = vl;
            uint4 wh = *(const uint4*)(WhB + (size_t)row*256 + kofs + col);
            uint4 wl = *(const uint4*)(WlB + (size_t)row*256 + kofs + col);
            *(uint4*)(sm + 2*128*P + row*P + col) = wh;
            *(uint4*)(sm + 3*128*P + row*P + col) = wl;
        }
        __syncthreads();
        #pragma unroll
        for (int ks = 0; ks < 4; ks++){
            uint32_t a_h[2][4], a_l[2][4], bw[4][4];
            #pragma unroll
            for (int i = 0; i < 2; i++){
                uint32_t addr = sb + (uint32_t)(((wm*32 + i*16 + ar)*P + ks*16 + ac8*8)*2);
                ldsm_x4(a_h[i], addr);
                ldsm_x4(a_l[i], addr + SZ);
            }
            #pragma unroll
            for (int qd = 0; qd < 4; qd++){
                uint32_t addr = sb + 2*SZ + (uint32_t)(((wn*64 + qd*16 + bnl)*P + ks*16 + bkh*8)*2);
                ldsm_x4(bw[qd], addr);
            }
            #pragma unroll
            for (int i = 0; i < 2; i++)
                #pragma unroll
                for (int j = 0; j < 8; j++)
                    mma16816(acc[i][j], a_h[i], &bw[j>>1][(j&1)*2]);
            #pragma unroll
            for (int i = 0; i < 2; i++)
                #pragma unroll
                for (int j = 0; j < 8; j++)
                    mma16816(acc[i][j], a_l[i], &bw[j>>1][(j&1)*2]);
            #pragma unroll
            for (int qd = 0; qd < 4; qd++){
                uint32_t addr = sb + 3*SZ + (uint32_t)(((wn*64 + qd*16 + bnl)*P + ks*16 + bkh*8)*2);
                ldsm_x4(bw[qd], addr);
            }
            #pragma unroll
            for (int i = 0; i < 2; i++)
                #pragma unroll
                for (int j = 0; j < 8; j++)
                    mma16816(acc[i][j], a_h[i], &bw[j>>1][(j&1)*2]);
        }
        __syncthreads();
    }

    // epilogue: D frag lane mapping: rows g=lane>>2 (+8), cols 2*(lane&3)+{0,1}
    const int cr = lane >> 2, cc = (lane & 3)*2;
    #pragma unroll
    for (int i = 0; i < 2; i++){
        #pragma unroll
        for (int rr = 0; rr < 2; rr++){
            int grow = row0 + wm*32 + i*16 + rr*8 + cr;
            if (grow >= M) continue;
            #pragma unroll
            for (int j = 0; j < 8; j++){
                int gcol = col0 + wn*64 + j*8 + cc;
                float v0 = acc[i][j][rr*2+0];
                float v1 = acc[i][j][rr*2+1];
                if (MODE == 0){
                    float2 f; f.x = v0; f.y = v1;
                    *(float2*)(Cf + cStride*blockIdx.z + (size_t)grow*256 + gcol) = f;
                } else if (MODE == 1){
                    v0 = lrelu01(v0 + bias[gcol]);
                    v1 = lrelu01(v1 + bias[gcol+1]);
                    bf16 h0, l0, h1, l1;
                    split2(v0, h0, l0); split2(v1, h1, l1);
                    Ch[(size_t)grow*256 + gcol]   = h0; Ch[(size_t)grow*256 + gcol+1] = h1;
                    Cl[(size_t)grow*256 + gcol]   = l0; Cl[(size_t)grow*256 + gcol+1] = l1;
                } else {
                    float2 f; f.x = v0 + bias[gcol]; f.y = v1 + bias[gcol+1];
                    *(float2*)(Cf + (size_t)grow*256 + gcol) = f;
                }
            }
        }
    }
}

// ---------------- wqk fold + small projection GEMM ----------------
__global__ void make_wqk(const float* __restrict__ w, const float* __restrict__ q,
                         const float* __restrict__ km)
{
    int idx = blockIdx.x*blockDim.x + threadIdx.x;
    int kk  = idx >> 6;
    int j   = idx & 63;
    int isK = (j >= 32);
    int rh  = isK ? j - 32 : j;
    int r   = rh >> 2, h = rh & 3;
    const float* wm = w + ((size_t)r*256 + kk)*256;
    const float* qm = isK ? km : q;
    float a = 0.f;
    #pragma unroll 8
    for (int o = 0; o < 256; o++) a += wm[o]*qm[o*4 + h];
    g_wqk[kk*64 + j] = a;
}

__global__ void gemm_k256_n64(const float* __restrict__ A, const float* __restrict__ W,
                              float* __restrict__ C, int M)
{
    constexpr int BM = 64, BK = 16, BN = 64;
    constexpr int TN = 4, TM = 4;
    __shared__ float As[BK][BM + 4];
    __shared__ float Ws[BK][BN];
    int row0 = blockIdx.x*BM;
    int t  = threadIdx.x;
    int tx = t & 15, ty = t >> 4;
    float acc[TM][TN] = {};
    int aRow = t >> 2;
    int aK4  = (t & 3) * 4;
    for (int k0 = 0; k0 < 256; k0 += BK){
        float4 av = make_float4(0.f,0.f,0.f,0.f);
        int gr = row0 + aRow;
        if (gr < M) av = *(const float4*)(A + (size_t)gr*256 + k0 + aK4);
        As[aK4+0][aRow] = av.x; As[aK4+1][aRow] = av.y;
        As[aK4+2][aRow] = av.z; As[aK4+3][aRow] = av.w;
        {
            int kk = t / 16, j4 = (t % 16) * 4;
            *(float4*)&Ws[kk][j4] = *(const float4*)(W + (size_t)(k0+kk)*64 + j4);
        }
        __syncthreads();
        #pragma unroll
        for (int kk = 0; kk < BK; kk++){
            float a[TM], bb[TN];
            #pragma unroll
            for (int i = 0; i < TM; i++) a[i] = As[kk][ty*TM + i];
            #pragma unroll
            for (int j = 0; j < TN; j++) bb[j] = Ws[kk][tx*TN + j];
            #pragma unroll
            for (int i = 0; i < TM; i++)
                #pragma unroll
                for (int j = 0; j < TN; j++) acc[i][j] += a[i]*bb[j];
        }
        __syncthreads();
    }
    #pragma unroll
    for (int i = 0; i < TM; i++){
        int gr = row0 + ty*TM + i;
        if (gr >= M) continue;
        #pragma unroll
        for (int j = 0; j < TN; j++)
            C[(size_t)gr*64 + tx*TN + j] = acc[i][j];
    }
}

// ---------------- CSR build ----------------
__global__ void zero_deg(){
    int i = blockIdx.x*blockDim.x + threadIdx.x;
    if (i < NN) g_deg[i] = 0;
}
__global__ void hist(const int* __restrict__ dst){
    int e = blockIdx.x*blockDim.x + threadIdx.x;
    if (e < EE) atomicAdd(&g_deg[dst[e]], 1);
}
__global__ void scan_rowptr(){
    __shared__ int part[1024];
    int t = threadIdx.x;
    int beg = t*20, end = beg + 20; if (end > NN) end = NN;
    int s = 0;
    for (int i = beg; i < end; i++) s += g_deg[i];
    part[t] = s;
    __syncthreads();
    for (int off = 1; off < 1024; off <<= 1){
        int v = 0;
        if (t >= off) v = part[t - off];
        __syncthreads();
        part[t] += v;
        __syncthreads();
    }
    int run = (t == 0) ? 0 : part[t-1];
    for (int i = beg; i < end; i++){
        g_rowptr[i] = run;
        g_cur[i]    = run;
        run += g_deg[i];
    }
}
__global__ void scatter(const int* __restrict__ dst){
    int e = blockIdx.x*blockDim.x + threadIdx.x;
    if (e >= EE) return;
    int slot = atomicAdd(&g_cur[dst[e]], 1);
    g_eid[slot] = e;
}

// ---------------- fused per-destination attention + aggregation ----------------
__global__ void edge_fused(const int* __restrict__ src, const int* __restrict__ et,
                           const float* __restrict__ bias,
                           const float* __restrict__ skip,   // nullable
                           float* __restrict__ out,
                           bf16* __restrict__ oh, bf16* __restrict__ ol)  // nullable
{
    const int d = blockIdx.x;
    const int t = threadIdx.x;          // 128
    const int wid  = t >> 5, lane = t & 31;
    const int base = g_rowptr[d], deg = g_deg[d];
    const int h0 = t >> 6;
    const int h1 = 2 + (t >> 6);

    __shared__ float sl[128][4];
    __shared__ int   ssrc[128];
    __shared__ int   srel[128];
    __shared__ float redm[4][4];
    __shared__ float reds[4][4];

    float acc0 = 0.f, acc1 = 0.f;
    float m[4], ssum[4];
    #pragma unroll
    for (int h = 0; h < 4; h++){ m[h] = -1e30f; ssum[h] = 0.f; }

    for (int c0 = 0; c0 < deg; c0 += 128){
        int n = deg - c0; if (n > 128) n = 128;
        float l[4];
        if (t < n){
            int e = g_eid[base + c0 + t];
            int s = src[e], r = et[e];
            ssrc[t] = s; srel[t] = r;
            const float* qv = g_s + (size_t)d*64 + r*4;
            const float* kv = g_s + (size_t)s*64 + 32 + r*4;
            #pragma unroll
            for (int h = 0; h < 4; h++){
                float v = qv[h] + kv[h];
                l[h] = v > 0.f ? v : 0.2f*v;
            }
        } else {
            #pragma unroll
            for (int h = 0; h < 4; h++) l[h] = -1e30f;
        }
        float lm[4];
        #pragma unroll
        for (int h = 0; h < 4; h++){
            float v = l[h];
            #pragma unroll
            for (int o = 16; o; o >>= 1) v = fmaxf(v, __shfl_xor_sync(0xffffffffu, v, o));
            lm[h] = v;
        }
        if (lane == 0){
            #pragma unroll
            for (int h = 0; h < 4; h++) redm[wid][h] = lm[h];
        }
        __syncthreads();
        float newm[4], scale[4];
        #pragma unroll
        for (int h = 0; h < 4; h++){
            float cm = fmaxf(fmaxf(redm[0][h], redm[1][h]), fmaxf(redm[2][h], redm[3][h]));
            newm[h]  = fmaxf(m[h], cm);
            scale[h] = __expf(m[h] - newm[h]);
            m[h]     = newm[h];
            ssum[h] *= scale[h];
        }
        acc0 *= scale[h0];
        acc1 *= scale[h1];
        float es[4];
        #pragma unroll
        for (int h = 0; h < 4; h++){
            float e = (t < n) ? __expf(l[h] - newm[h]) : 0.f;
            sl[t][h] = e;
            #pragma unroll
            for (int o = 16; o; o >>= 1) e += __shfl_xor_sync(0xffffffffu, e, o);
            es[h] = e;
        }
        if (lane == 0){
            #pragma unroll
            for (int h = 0; h < 4; h++) reds[wid][h] = es[h];
        }
        __syncthreads();
        #pragma unroll
        for (int h = 0; h < 4; h++)
            ssum[h] += reds[0][h] + reds[1][h] + reds[2][h] + reds[3][h];

        for (int i = 0; i < n; i++){
            const float* row = g_xw + ((size_t)srel[i]*NN + ssrc[i])*HD;
            acc0 += sl[i][h0] * row[t];
            acc1 += sl[i][h1] * row[t + 128];
        }
        __syncthreads();
    }

    float inv0 = 1.f / fmaxf(ssum[h0], 1e-16f);
    float inv1 = 1.f / fmaxf(ssum[h1], 1e-16f);
    float v0 = acc0*inv0 + bias[t];
    float v1 = acc1*inv1 + bias[t + 128];
    if (skip){
        v0 += skip[(size_t)d*HD + t];
        v1 += skip[(size_t)d*HD + t + 128];
    }
    v0 = lrelu01(v0); v1 = lrelu01(v1);
    out[(size_t)d*HD + t]       = v0;
    out[(size_t)d*HD + t + 128] = v1;
    if (oh){
        bf16 h, l;
        split2(v0, h, l); oh[(size_t)d*HD + t]       = h; ol[(size_t)d*HD + t]       = l;
        split2(v1, h, l); oh[(size_t)d*HD + t + 128] = h; ol[(size_t)d*HD + t + 128] = l;
    }
}

// ---------------- host ----------------
template<typename T>
static T* sym(const void* s){ void* p = nullptr; cudaGetSymbolAddress(&p, s); return (T*)p; }

extern "C" void kernel_launch(void* const* d_in, const int* in_sizes, int n_in,
                              void* d_out, int out_size)
{
    int iKG, iCCLE, iNID, iEI, iET, iCW1, iCB1, iCW2, iCB2,
        iW1, iQ1, iK1, iB1, iW2, iQ2, iK2, iB2, iSW1, iSB1, iSW2, iSB2;
    if (in_sizes[2] == NN){
        iKG=0; iCCLE=1; iNID=2; iEI=3; iET=4;
        iCW1=5; iCB1=6; iCW2=7; iCB2=8;
        iW1=9; iQ1=10; iK1=11; iB1=12;
        iW2=13; iQ2=14; iK2=15; iB2=16;
        iSW1=17; iSB1=18; iSW2=19; iSB2=20;
    } else {
        iKG=0; iCCLE=1;
        iCW1=2; iCB1=3; iCW2=4; iCB2=5;
        iW1=6; iQ1=7; iK1=8; iB1=9;
        iW2=10; iQ2=11; iK2=12; iB2=13;
        iSW1=14; iSB1=15; iSW2=16; iSB2=17;
        iNID=18; iEI=19; iET=20;
    }
    const float* kg   = (const float*)d_in[iKG];
    const float* ccle = (const float*)d_in[iCCLE];
    const int*   nid  = (const int*)  d_in[iNID];
    const int*   ei   = (const int*)  d_in[iEI];
    const int*   et   = (const int*)  d_in[iET];
    const int*   src  = ei;
    const int*   dst  = ei + EE;
    const float* cw1 = (const float*)d_in[iCW1]; const float* cb1 = (const float*)d_in[iCB1];
    const float* cw2 = (const float*)d_in[iCW2]; const float* cb2 = (const float*)d_in[iCB2];
    const float* w1  = (const float*)d_in[iW1];  const float* q1  = (const float*)d_in[iQ1];
    const float* k1  = (const float*)d_in[iK1];  const float* b1  = (const float*)d_in[iB1];
    const float* w2  = (const float*)d_in[iW2];  const float* q2  = (const float*)d_in[iQ2];
    const float* k2  = (const float*)d_in[iK2];  const float* b2  = (const float*)d_in[iB2];
    const float* sw1 = (const float*)d_in[iSW1]; const float* sb1 = (const float*)d_in[iSB1];
    const float* sw2 = (const float*)d_in[iSW2]; const float* sb2 = (const float*)d_in[iSB2];

    float* pxin = sym<float>(g_xin);  float* pxw  = sym<float>(g_xw);
    float* ps   = sym<float>(g_s);    float* pwqk = sym<float>(g_wqk);
    float* px1  = sym<float>(g_x1);   float* pskp = sym<float>(g_skp);
    bf16* pxinh = sym<bf16>(g_xinh);  bf16* pxinl = sym<bf16>(g_xinl);
    bf16* px1h  = sym<bf16>(g_x1h);   bf16* px1l  = sym<bf16>(g_x1l);
    bf16* phsh  = sym<bf16>(g_hsh);   bf16* phsl  = sym<bf16>(g_hsl);
    bf16* pw1h  = sym<bf16>(g_w1h);   bf16* pw1l  = sym<bf16>(g_w1l);
    bf16* pw2h  = sym<bf16>(g_w2h);   bf16* pw2l  = sym<bf16>(g_w2l);
    bf16* psw1h = sym<bf16>(g_sw1h);  bf16* psw1l = sym<bf16>(g_sw1l);
    bf16* psw2h = sym<bf16>(g_sw2h);  bf16* psw2l = sym<bf16>(g_sw2l);

    const int SMEM_HM = 4*128*72*2;   // 73728 B
    cudaFuncSetAttribute(hmma_gemm<0>, cudaFuncAttributeMaxDynamicSharedMemorySize, SMEM_HM);
    cudaFuncSetAttribute(hmma_gemm<1>, cudaFuncAttributeMaxDynamicSharedMemorySize, SMEM_HM);
    cudaFuncSetAttribute(hmma_gemm<2>, cudaFuncAttributeMaxDynamicSharedMemorySize, SMEM_HM);

    const int gM  = (NN + 127)/128;   // 157
    const int gM64= (NN + 63)/64;
    const int gE  = (EE + 255)/256;
    dim3 tb(32, 8);

    // prep: x_in (+splits), CSR, W splits
    build_xin<<<NN, 128>>>(kg, ccle, nid, cw1, cb1, cw2, cb2);
    zero_deg<<<(NN+255)/256, 256>>>();
    hist<<<gE, 256>>>(dst);
    scan_rowptr<<<1, 1024>>>();
    scatter<<<gE, 256>>>(dst);
    splitW<<<dim3(8,8,RR), tb>>>(w1, pw1h, pw1l);
    splitW<<<dim3(8,8,RR), tb>>>(w2, pw2h, pw2l);
    splitW<<<dim3(8,8,1),  tb>>>(sw1, psw1h, psw1l);
    splitW<<<dim3(8,8,1),  tb>>>(sw2, psw2h, psw2l);

    // skip path
    hmma_gemm<1><<<dim3(gM,2,1), 256, SMEM_HM>>>(pxinh, pxinl, psw1h, psw1l,
                                                 nullptr, phsh, phsl, NN, sb1, 0, 0);
    hmma_gemm<2><<<dim3(gM,2,1), 256, SMEM_HM>>>(phsh, phsl, psw2h, psw2l,
                                                 pskp, nullptr, nullptr, NN, sb2, 0, 0);

    // ===== layer 1 =====
    make_wqk<<<64, 256>>>(w1, q1, k1);
    gemm_k256_n64<<<gM64, 256>>>(pxin, pwqk, ps, NN);
    hmma_gemm<0><<<dim3(gM,2,RR), 256, SMEM_HM>>>(pxinh, pxinl, pw1h, pw1l,
                                                  pxw, nullptr, nullptr, NN, nullptr,
                                                  (size_t)65536, (size_t)NN*HD);
    edge_fused<<<NN, 128>>>(src, et, b1, nullptr, px1, px1h, px1l);

    // ===== layer 2 =====
    make_wqk<<<64, 256>>>(w2, q2, k2);
    gemm_k256_n64<<<gM64, 256>>>(px1, pwqk, ps, NN);
    hmma_gemm<0><<<dim3(gM,2,RR), 256, SMEM_HM>>>(px1h, px1l, pw2h, pw2l,
                                                  pxw, nullptr, nullptr, NN, nullptr,
                                                  (size_t)65536, (size_t)NN*HD);
    edge_fused<<<NN, 128>>>(src, et, b2, pskp, (float*)d_out, nullptr, nullptr);
}